// round 15
// baseline (speedup 1.0000x reference)
#include <cuda_runtime.h>

// LR_23029614641373: logit = W[u] + W[6040+m] + b; out = [1-p, p]
// Lineage: R10 depth-2 -> R12 width-2 -> R13 width-4 -> R14 folded math
// (wall 12.45us, ncu 12.35us). SINGLE CHANGE this round: predicate-free
// main loop. All threads run nfull = n2/(stride*WIDTH) uniform stages
// with NO bounds checks (max index provably < n2), killing the 8 ISETPs
// + 8 predicated-op guards per stage that made alu=19%. Ragged remainder
// (<WIDTH elements/thread) handled in a short checked epilogue.
// Math (folded table): sw[i] = -log2(e)*(w[i]+b/2);
//   s=sw[u]+sw[m']; e=ex2(s); p=rcp(1+e); 1-p=e*p.

#define N_USERS 6040
#define TABLE   9923
#define NTHREADS 512
#define NBLK_SM  2
#define WIDTH    4

__device__ __forceinline__ float ex2_fast(float x) {
    float y; asm("ex2.approx.f32 %0, %1;" : "=f"(y) : "f"(x)); return y;
}
__device__ __forceinline__ float rcp_fast(float x) {
    float y; asm("rcp.approx.f32 %0, %1;" : "=f"(y) : "f"(x)); return y;
}

__device__ __forceinline__ float4 two_rows_exp(const float* __restrict__ sw,
                                               int4 v) {
    float s0 = sw[v.x] + sw[N_USERS + v.y];   // = -logit0 * log2(e)
    float s1 = sw[v.z] + sw[N_USERS + v.w];
    float e0 = ex2_fast(s0);                  // = exp(-logit0)
    float e1 = ex2_fast(s1);
    float p0 = rcp_fast(1.0f + e0);
    float p1 = rcp_fast(1.0f + e1);
    return make_float4(e0 * p0, p0, e1 * p1, p1);
}

__global__ void __launch_bounds__(NTHREADS, NBLK_SM) lr_smem_kernel(
    const int4* __restrict__ x2,      // [n2] two (u,m) rows per int4
    const float* __restrict__ w,      // [9923]
    const float* __restrict__ bptr,   // [1]
    float4* __restrict__ out,         // [n2] {1-p0,p0,1-p1,p1}
    int n2)
{
    __shared__ float sw[TABLE];
    {
        const float kk = -1.44269504088896340736f;  // -log2(e)
        const float hb = 0.5f * __ldg(bptr);
        #pragma unroll
        for (int i = threadIdx.x; i < TABLE; i += NTHREADS)
            sw[i] = kk * (w[i] + hb);
    }
    __syncthreads();

    const int stride = gridDim.x * blockDim.x;
    const int step   = stride * WIDTH;
    const int t      = blockIdx.x * blockDim.x + threadIdx.x;
    const int nfull  = n2 / step;     // uniform full stages, no bounds checks

    int base = t;
    int4 v[WIDTH];

    if (nfull > 0) {
        #pragma unroll
        for (int k = 0; k < WIDTH; k++)
            v[k] = x2[base + k * stride];

        for (int s = 0; s < nfull; s++) {
            int4 nv[WIDTH];
            if (s + 1 < nfull) {               // uniform branch
                #pragma unroll
                for (int k = 0; k < WIDTH; k++)
                    nv[k] = x2[base + step + k * stride];
            }
            #pragma unroll
            for (int k = 0; k < WIDTH; k++)
                out[base + k * stride] = two_rows_exp(sw, v[k]);

            base += step;
            #pragma unroll
            for (int k = 0; k < WIDTH; k++) v[k] = nv[k];
        }
    }

    // ragged tail: < WIDTH iterations per thread, bounds-checked
    for (int idx = t + nfull * step; idx < n2; idx += stride)
        out[idx] = two_rows_exp(sw, x2[idx]);
}

// Rare odd-row tail (B is even in this dataset).
__global__ void lr_tail_kernel(
    const int2* __restrict__ x,
    const float* __restrict__ w,
    const float* __restrict__ bptr,
    float2* __restrict__ out,
    int start, int n)
{
    int i = start + blockIdx.x * blockDim.x + threadIdx.x;
    if (i >= n) return;
    int2 v = x[i];
    float l = __ldg(w + v.x) + __ldg(w + N_USERS + v.y) + __ldg(bptr);
    float e = ex2_fast(-1.44269504088896340736f * l);
    float p = rcp_fast(1.0f + e);
    out[i] = make_float2(e * p, p);
}

extern "C" void kernel_launch(void* const* d_in, const int* in_sizes, int n_in,
                              void* d_out, int out_size)
{
    const int*   x = (const int*)d_in[0];     // [B, 2] int32
    const float* W = (const float*)d_in[1];   // [1, 9923]
    const float* b = (const float*)d_in[2];   // [1]
    float* out = (float*)d_out;               // [B, 2]

    int B  = in_sizes[0] / 2;
    int n2 = B / 2;

    if (n2 > 0) {
        int max_blocks = 148 * NBLK_SM;       // 296
        int blocks = (n2 + NTHREADS - 1) / NTHREADS;
        if (blocks > max_blocks) blocks = max_blocks;
        lr_smem_kernel<<<blocks, NTHREADS>>>(
            (const int4*)x, W, b, (float4*)out, n2);
    }
    if (B & 1) {
        lr_tail_kernel<<<1, 32>>>(
            (const int2*)x, W, b, (float2*)out, 2 * n2, B);
    }
}

// round 16
// speedup vs baseline: 1.0552x; 1.0552x over previous
#include <cuda_runtime.h>

// LR_23029614641373: logit = W[u] + W[6040+m] + b; out = [1-p, p]
// Lineage: ...R13 width-4 -> R14 folded math (wall 12.45, ncu 12.35 best).
// R15 lesson: removing predicates at STAGE granularity left a 13% slow
// ragged tail -> regression. This round quantizes at ELEMENT granularity:
//   cnt = n2/stride  -> every thread owns exactly cnt in-bounds elements
//   nst = cnt/WIDTH pipelined predicate-free stages
//   + (cnt%WIDTH) uniform singles + <=1 checked element (n2%stride thrds)
// Zero per-element ISETPs in the hot loop (was alu=19%), no slow phase.
// Math (folded table): sw[i]=-log2(e)*(w[i]+b/2); e=ex2(sw[u]+sw[m']);
// p=rcp(1+e); 1-p=e*p.

#define N_USERS 6040
#define TABLE   9923
#define NTHREADS 512
#define NBLK_SM  2
#define WIDTH    4

__device__ __forceinline__ float ex2_fast(float x) {
    float y; asm("ex2.approx.f32 %0, %1;" : "=f"(y) : "f"(x)); return y;
}
__device__ __forceinline__ float rcp_fast(float x) {
    float y; asm("rcp.approx.f32 %0, %1;" : "=f"(y) : "f"(x)); return y;
}

__device__ __forceinline__ float4 two_rows_exp(const float* __restrict__ sw,
                                               int4 v) {
    float s0 = sw[v.x] + sw[N_USERS + v.y];   // = -logit0 * log2(e)
    float s1 = sw[v.z] + sw[N_USERS + v.w];
    float e0 = ex2_fast(s0);                  // = exp(-logit0)
    float e1 = ex2_fast(s1);
    float p0 = rcp_fast(1.0f + e0);
    float p1 = rcp_fast(1.0f + e1);
    return make_float4(e0 * p0, p0, e1 * p1, p1);
}

__global__ void __launch_bounds__(NTHREADS, NBLK_SM) lr_smem_kernel(
    const int4* __restrict__ x2,      // [n2] two (u,m) rows per int4
    const float* __restrict__ w,      // [9923]
    const float* __restrict__ bptr,   // [1]
    float4* __restrict__ out,         // [n2] {1-p0,p0,1-p1,p1}
    int n2)
{
    __shared__ float sw[TABLE];
    {
        const float kk = -1.44269504088896340736f;  // -log2(e)
        const float hb = 0.5f * __ldg(bptr);
        #pragma unroll
        for (int i = threadIdx.x; i < TABLE; i += NTHREADS)
            sw[i] = kk * (w[i] + hb);
    }
    __syncthreads();

    const int stride = gridDim.x * blockDim.x;
    const int step   = stride * WIDTH;
    const int t      = blockIdx.x * blockDim.x + threadIdx.x;

    const int cnt = n2 / stride;      // uniform per-thread element count
    const int nst = cnt / WIDTH;      // full pipelined stages

    int base = t;

    if (nst > 0) {
        int4 v[WIDTH];
        #pragma unroll
        for (int k = 0; k < WIDTH; k++)
            v[k] = x2[base + k * stride];           // no bounds checks

        for (int s = 0; s < nst; s++) {
            int4 nv[WIDTH];
            if (s + 1 < nst) {                      // uniform branch
                #pragma unroll
                for (int k = 0; k < WIDTH; k++)
                    nv[k] = x2[base + step + k * stride];
            }
            #pragma unroll
            for (int k = 0; k < WIDTH; k++)
                out[base + k * stride] = two_rows_exp(sw, v[k]);

            base += step;
            #pragma unroll
            for (int k = 0; k < WIDTH; k++) v[k] = nv[k];
        }
    }

    // uniform leftover singles: cnt % WIDTH elements, still no checks
    #pragma unroll
    for (int k = 0; k < WIDTH - 1; k++) {
        int j = nst * WIDTH + k;
        if (j < cnt)                                 // uniform predicate
            out[t + j * stride] = two_rows_exp(sw, x2[t + j * stride]);
    }

    // ragged final element: only threads with t < n2 % stride
    int idx = t + cnt * stride;
    if (idx < n2)
        out[idx] = two_rows_exp(sw, x2[idx]);
}

// Rare odd-row tail (B is even in this dataset).
__global__ void lr_tail_kernel(
    const int2* __restrict__ x,
    const float* __restrict__ w,
    const float* __restrict__ bptr,
    float2* __restrict__ out,
    int start, int n)
{
    int i = start + blockIdx.x * blockDim.x + threadIdx.x;
    if (i >= n) return;
    int2 v = x[i];
    float l = __ldg(w + v.x) + __ldg(w + N_USERS + v.y) + __ldg(bptr);
    float e = ex2_fast(-1.44269504088896340736f * l);
    float p = rcp_fast(1.0f + e);
    out[i] = make_float2(e * p, p);
}

extern "C" void kernel_launch(void* const* d_in, const int* in_sizes, int n_in,
                              void* d_out, int out_size)
{
    const int*   x = (const int*)d_in[0];     // [B, 2] int32
    const float* W = (const float*)d_in[1];   // [1, 9923]
    const float* b = (const float*)d_in[2];   // [1]
    float* out = (float*)d_out;               // [B, 2]

    int B  = in_sizes[0] / 2;
    int n2 = B / 2;

    if (n2 > 0) {
        int max_blocks = 148 * NBLK_SM;       // 296
        int blocks = (n2 + NTHREADS - 1) / NTHREADS;
        if (blocks > max_blocks) blocks = max_blocks;
        lr_smem_kernel<<<blocks, NTHREADS>>>(
            (const int4*)x, W, b, (float4*)out, n2);
    }
    if (B & 1) {
        lr_tail_kernel<<<1, 32>>>(
            (const int2*)x, W, b, (float2*)out, 2 * n2, B);
    }
}